// round 16
// baseline (speedup 1.0000x reference)
#include <cuda_runtime.h>
#include <cuda_fp16.h>
#include <math.h>
#include <float.h>
#include <stdint.h>

// ---------------- problem constants ----------------
#define B_ROWS   1024
#define EMB_D    512
#define NCLASS   100000
#define CT       128                              // class tile (N)
#define NTILES   ((NCLASS + CT - 1) / CT)         // 782
#define MBLK     8                                // B_ROWS / 128
#define TOTAL_ITEMS (MBLK * NTILES)               // 6256
#define NUM_CTAS 296                              // 2 per SM, persistent
#define SCALE_F  30.0f
#define LOG2E_F  1.4426950408889634f
#define LN2_F    0.6931471805599453f

// ArcFace margin constants (margin = 0.3)
#define COS_M 0.9553364891256061f
#define SIN_M 0.2955202066613396f
#define TH_C  (-0.9553364891256061f)
#define MM_C  0.08865606199840186f

// ---------------- scratch ----------------
// g_wh holds weight * (30*log2(e)/||w||): GEMM accumulators are log2-logits.
__device__ __half g_wh[(size_t)NCLASS * EMB_D];
__device__ __half g_eh[B_ROWS * EMB_D];           // fp16 embeddings
__device__ float  g_inv_norm[NCLASS];             // 30/||w|| (exact label path)
__device__ float  g_m[B_ROWS * NTILES];           // per-tile max (log2 domain)
__device__ float  g_s[B_ROWS * NTILES];           // per-tile sum 2^(l-m)
__device__ float  g_nll[B_ROWS];
__device__ int    g_lab_is64;

// ---------------- helpers ----------------
__device__ __forceinline__ uint32_t smem_u32(const void* p) {
    uint32_t a;
    asm("{ .reg .u64 t; cvta.to.shared.u64 t, %1; cvt.u32.u64 %0, t; }" : "=r"(a) : "l"(p));
    return a;
}
__device__ __forceinline__ void cp16u(uint32_t dst, const void* src) {
    asm volatile("cp.async.cg.shared.global [%0], [%1], 16;" :: "r"(dst), "l"(src));
}
#define CP_COMMIT()  asm volatile("cp.async.commit_group;" ::: "memory")
#define CP_WAIT(n)   asm volatile("cp.async.wait_group %0;" :: "n"(n) : "memory")

__device__ __forceinline__ void mma_16816(float* c, const uint32_t* a, uint32_t b0, uint32_t b1) {
    asm volatile(
        "mma.sync.aligned.m16n8k16.row.col.f32.f16.f16.f32 "
        "{%0,%1,%2,%3}, {%4,%5,%6,%7}, {%8,%9}, {%0,%1,%2,%3};"
        : "+f"(c[0]), "+f"(c[1]), "+f"(c[2]), "+f"(c[3])
        : "r"(a[0]), "r"(a[1]), "r"(a[2]), "r"(a[3]), "r"(b0), "r"(b1));
}
__device__ __forceinline__ void ldm_x4(uint32_t* r, uint32_t addr) {
    asm volatile("ldmatrix.sync.aligned.m8n8.x4.shared.b16 {%0,%1,%2,%3}, [%4];"
                 : "=r"(r[0]), "=r"(r[1]), "=r"(r[2]), "=r"(r[3]) : "r"(addr));
}

// smem geometry: fp16, K-chunk 64, padded row stride 72 halves (144 B)
// stage = A(128 rows) + B(128 rows); 3-stage ring, 1 barrier per chunk.
#define RS_H        72
#define TILE_B      (128 * RS_H * 2)               // 18432 B per operand
#define STAGE_B     (2 * TILE_B)                   // 36864 B
#define NSTAGE      3
#define PART_OFF    (NSTAGE * STAGE_B)             // 110592
#define SMEM_DYN    (PART_OFF + 2048)              // 112640 B (2 CTAs/SM: 220 KB)

// ---------------------------------------------------------------------------
// Kernel 0: fused prepass (one launch):
//  blocks [0, WBLK)       : per-class norm + fp16 convert (30*log2e/||w|| folded)
//  blocks [WBLK, WBLK+EB) : embeddings fp32 -> fp16
//  block  WBLK+EBLK       : labels dtype probe (int64 vs int32)
// ---------------------------------------------------------------------------
#define WBLK ((NCLASS + 7) / 8)                    // 12500
#define EBLK (B_ROWS * EMB_D / 4 / 256)            // 512

__global__ __launch_bounds__(256) void prepass_kernel(const float* __restrict__ weight,
                                                      const float* __restrict__ emb,
                                                      const void* __restrict__ labels) {
    if (blockIdx.x < WBLK) {
        int gid  = blockIdx.x * 256 + threadIdx.x;
        int c    = gid >> 5;
        int lane = gid & 31;
        if (c >= NCLASS) return;
        const float* w = weight + (size_t)c * EMB_D;
        float4 v[4];
        float s = 0.f;
        #pragma unroll
        for (int i = 0; i < 4; i++) {
            v[i] = *(const float4*)&w[lane * 4 + i * 128];
            s += v[i].x * v[i].x + v[i].y * v[i].y + v[i].z * v[i].z + v[i].w * v[i].w;
        }
        #pragma unroll
        for (int o = 16; o > 0; o >>= 1) s += __shfl_xor_sync(0xffffffffu, s, o);
        float r  = rsqrtf(s);
        if (lane == 0) g_inv_norm[c] = SCALE_F * r;
        float sc = SCALE_F * LOG2E_F * r;          // log2-domain fold
        __half* dst = g_wh + (size_t)c * EMB_D;
        #pragma unroll
        for (int i = 0; i < 4; i++) {
            __half2 h0 = __floats2half2_rn(v[i].x * sc, v[i].y * sc);
            __half2 h1 = __floats2half2_rn(v[i].z * sc, v[i].w * sc);
            *(uint2*)&dst[lane * 4 + i * 128] = make_uint2(*(uint32_t*)&h0, *(uint32_t*)&h1);
        }
    } else if (blockIdx.x < WBLK + EBLK) {
        int i = (blockIdx.x - WBLK) * 256 + threadIdx.x;   // one float4 per thread
        float4 v = *(const float4*)&emb[i * 4];
        __half2 h0 = __floats2half2_rn(v.x, v.y);
        __half2 h1 = __floats2half2_rn(v.z, v.w);
        *(uint2*)&g_eh[i * 4] = make_uint2(*(uint32_t*)&h0, *(uint32_t*)&h1);
    } else {
        // labels dtype probe: read first 512 elements as int64 (4 KB, safe
        // even for an int32 buffer). All in range -> int64, else int32.
        __shared__ int bad;
        if (threadIdx.x == 0) bad = 0;
        __syncthreads();
        #pragma unroll
        for (int i = 0; i < 2; i++) {
            long long v = ((const long long*)labels)[threadIdx.x * 2 + i];
            if (v < 0 || v >= NCLASS) atomicOr(&bad, 1);
        }
        __syncthreads();
        if (threadIdx.x == 0) g_lab_is64 = bad ? 0 : 1;
    }
}

// ---------------------------------------------------------------------------
// Kernel 1: PERSISTENT fp16 mma GEMM + fused logsumexp (log2 domain).
// grid = 296 CTAs (2/SM), 256 threads (8 warps: 4M x 2N), warp tile 32x64.
// Each CTA streams a flat chunk sequence over ~21 work items
// (item -> tile=item>>3, m=item&7; stride 296=8*37 keeps 8-CTA groups on one
// class tile -> B stays L2-hot). 3-stage cp.async ring never drains between
// tiles; epilogue of tile i overlaps fills of tile i+1.
// ---------------------------------------------------------------------------
__global__ __launch_bounds__(256, 2) void gemm_lse_h(void) {
    extern __shared__ __align__(16) char smc[];
    float*  sm_pm = (float*)(smc + PART_OFF);          // [128][2]
    float*  sm_ps = sm_pm + 256;

    const int tid = threadIdx.x;
    const int bid = blockIdx.x;

    const int wid  = tid >> 5, lane = tid & 31;
    const int wm   = wid & 3;
    const int wn   = wid >> 2;
    const int g    = lane >> 2, tig = lane & 3;

    const uint32_t smem_base = smem_u32(smc);

    // ldmatrix per-lane byte offsets within a stage
    const uint32_t a_off = ((uint32_t)(wm * 32 + (lane & 7) + ((lane >> 3) & 1) * 8) * RS_H
                            + ((lane >> 4) & 1) * 8) * 2;
    const uint32_t b_off = (uint32_t)TILE_B
                         + ((uint32_t)(wn * 64 + (lane & 7) + ((lane >> 4) & 1) * 8) * RS_H
                            + ((lane >> 3) & 1) * 8) * 2;

    // per-thread fill coordinates
    const int fr = tid >> 3;                     // base row 0..31
    const int fu = tid & 7;                      // 16B unit

    // chunk q -> item = bid + (q>>3)*NUM_CTAS, kt = q&7.
    auto load_stage = [&](int q, uint32_t sa) {
        const int item   = bid + (q >> 3) * NUM_CTAS;
        const int kt     = q & 7;
        const int m_base = (item & 7) * 128;
        const int c0     = (item >> 3) * CT;
        const int k0     = kt * 64;
        const uint32_t sb = sa + TILE_B;
        #pragma unroll
        for (int i = 0; i < 4; i++) {                       // A rows fr+32i
            int rr = fr + i * 32;
            cp16u(sa + (rr * RS_H + fu * 8) * 2,
                  g_eh + (size_t)(m_base + rr) * EMB_D + k0 + fu * 8);
        }
        #pragma unroll
        for (int i = 0; i < 4; i++) {                       // B rows, clamp source
            int rr = fr + i * 32;
            int c  = c0 + rr;
            if (c > NCLASS - 1) c = NCLASS - 1;             // epilogue masks OOB cols
            cp16u(sb + (rr * RS_H + fu * 8) * 2,
                  g_wh + (size_t)c * EMB_D + k0 + fu * 8);
        }
        CP_COMMIT();
    };

    float acc[2][8][4];
    #pragma unroll
    for (int mi = 0; mi < 2; mi++)
        #pragma unroll
        for (int ni = 0; ni < 8; ni++)
            #pragma unroll
            for (int q = 0; q < 4; q++) acc[mi][ni][q] = 0.f;

    auto consume = [&](uint32_t cur) {
        const uint32_t sA = cur + a_off;
        const uint32_t sB = cur + b_off;
        #pragma unroll
        for (int ks = 0; ks < 4; ks++) {
            const uint32_t kb = (uint32_t)ks * 32;     // 16 halves
            uint32_t a[2][4];
            ldm_x4(a[0], sA + kb);
            ldm_x4(a[1], sA + (16 * RS_H) * 2 + kb);
            #pragma unroll
            for (int nip = 0; nip < 4; nip++) {
                uint32_t br[4];
                ldm_x4(br, sB + (uint32_t)(nip * 16 * RS_H) * 2 + kb);
                mma_16816(acc[0][2 * nip],     a[0], br[0], br[1]);
                mma_16816(acc[1][2 * nip],     a[1], br[0], br[1]);
                mma_16816(acc[0][2 * nip + 1], a[0], br[2], br[3]);
                mma_16816(acc[1][2 * nip + 1], a[1], br[2], br[3]);
            }
        }
    };

    const int n_it = (TOTAL_ITEMS - bid + NUM_CTAS - 1) / NUM_CTAS;   // 21 or 22
    const int Q    = n_it * 8;

    const uint32_t ring_end = smem_base + NSTAGE * STAGE_B;
    uint32_t cur = smem_base;
    uint32_t pf  = smem_base + 2 * STAGE_B;

    load_stage(0, smem_base);
    load_stage(1, smem_base + STAGE_B);

    int item = bid;                               // item of the chunk being consumed

    #pragma unroll 1
    for (int q = 0; q < Q; q++) {
        if (q < Q - 1) { CP_WAIT(1); } else { CP_WAIT(0); }
        __syncthreads();        // all readers done with slot pf (held chunk q-1)
        if (q + 2 < Q) load_stage(q + 2, pf);
        consume(cur);
        cur += STAGE_B; if (cur == ring_end) cur = smem_base;
        pf  += STAGE_B; if (pf  == ring_end) pf  = smem_base;

        if ((q & 7) == 7) {
            // ---- epilogue for 'item' (fills for next tile already in flight)
            const int m_base = (item & 7) * 128;
            const int tIdx   = item >> 3;
            const int c0     = tIdx * CT;
            const bool full  = (c0 + CT) <= NCLASS;

            #pragma unroll
            for (int mi = 0; mi < 2; mi++) {
                #pragma unroll
                for (int half = 0; half < 2; half++) {
                    const int row = wm * 32 + mi * 16 + half * 8 + g;
                    float lv[16];
                    float mx = -FLT_MAX;
                    #pragma unroll
                    for (int ni = 0; ni < 8; ni++) {
                        float v0 = acc[mi][ni][half * 2 + 0];
                        float v1 = acc[mi][ni][half * 2 + 1];
                        if (!full) {
                            int col = wn * 64 + ni * 8 + 2 * tig;
                            if (c0 + col     >= NCLASS) v0 = -FLT_MAX;
                            if (c0 + col + 1 >= NCLASS) v1 = -FLT_MAX;
                        }
                        lv[ni * 2]     = v0;
                        lv[ni * 2 + 1] = v1;
                        mx = fmaxf(mx, fmaxf(v0, v1));
                    }
                    float ss = 0.f;
                    #pragma unroll
                    for (int j = 0; j < 16; j++) ss += exp2f(lv[j] - mx);
                    #pragma unroll
                    for (int d = 1; d <= 2; d <<= 1) {
                        float om = __shfl_xor_sync(0xffffffffu, mx, d);
                        float os = __shfl_xor_sync(0xffffffffu, ss, d);
                        float nm = fmaxf(mx, om);
                        ss = ss * exp2f(mx - nm) + os * exp2f(om - nm);
                        mx = nm;
                    }
                    if (tig == 0) {
                        sm_pm[row * 2 + wn] = mx;
                        sm_ps[row * 2 + wn] = ss;
                    }
                }
            }
            __syncthreads();
            if (tid < 128) {
                float m0 = sm_pm[tid * 2], m1 = sm_pm[tid * 2 + 1];
                float s0 = sm_ps[tid * 2], s1 = sm_ps[tid * 2 + 1];
                float M = fmaxf(m0, m1);
                float S = s0 * exp2f(m0 - M) + s1 * exp2f(m1 - M);
                g_m[(size_t)(m_base + tid) * NTILES + tIdx] = M;
                g_s[(size_t)(m_base + tid) * NTILES + tIdx] = S;
            }
            // reset accumulators for the next item
            #pragma unroll
            for (int mi = 0; mi < 2; mi++)
                #pragma unroll
                for (int ni = 0; ni < 8; ni++)
                    #pragma unroll
                    for (int qq = 0; qq < 4; qq++) acc[mi][ni][qq] = 0.f;
            item += NUM_CTAS;
        }
    }
}

// ---------------------------------------------------------------------------
// Kernel 3: one WARP per batch row: combine tile partials + exact label
// cosine + ArcFace correction. grid = B_ROWS/8, 256 threads.
// ---------------------------------------------------------------------------
__global__ __launch_bounds__(256) void finalize_rows_kernel(const float* __restrict__ emb,
                                                            const void* __restrict__ labels,
                                                            const float* __restrict__ weight) {
    const int wid  = threadIdx.x >> 5;
    const int lane = threadIdx.x & 31;
    const int b    = blockIdx.x * 8 + wid;

    long long lab;
    if (g_lab_is64) lab = ((const long long*)labels)[b];
    else            lab = (long long)((const int*)labels)[b];
    if (lab < 0) lab = 0;
    if (lab >= NCLASS) lab = NCLASS - 1;

    const float* e = emb + (size_t)b * EMB_D;
    const float* w = weight + (size_t)lab * EMB_D;
    float dot = 0.f;
    #pragma unroll
    for (int i = 0; i < 4; i++) {
        float4 ev = *(const float4*)&e[lane * 4 + i * 128];
        float4 wv = *(const float4*)&w[lane * 4 + i * 128];
        dot += ev.x * wv.x + ev.y * wv.y + ev.z * wv.z + ev.w * wv.w;
    }
    #pragma unroll
    for (int o = 16; o > 0; o >>= 1) dot += __shfl_xor_sync(0xffffffffu, dot, o);

    const float* gm = g_m + (size_t)b * NTILES;
    const float* gs = g_s + (size_t)b * NTILES;
    float M = -FLT_MAX;
    for (int t = lane; t < NTILES; t += 32) M = fmaxf(M, gm[t]);
    #pragma unroll
    for (int o = 16; o > 0; o >>= 1) M = fmaxf(M, __shfl_xor_sync(0xffffffffu, M, o));

    float S = 0.f;
    for (int t = lane; t < NTILES; t += 32) S += gs[t] * exp2f(gm[t] - M);
    #pragma unroll
    for (int o = 16; o > 0; o >>= 1) S += __shfl_xor_sync(0xffffffffu, S, o);

    if (lane == 0) {
        float cv = dot * g_inv_norm[lab] * (1.0f / SCALE_F);     // cosine
        float l_cos = SCALE_F * cv;                              // natural domain
        float sine  = sqrtf(fmaxf(0.f, fminf(1.f, 1.f - cv * cv)));
        float phi   = cv * COS_M - sine * SIN_M;
        if (!(cv > TH_C)) phi = cv - MM_C;
        float l_phi = SCALE_F * phi;
        float Sc = S - exp2f(l_cos * LOG2E_F - M) + exp2f(l_phi * LOG2E_F - M);
        g_nll[b] = (M + log2f(Sc)) * LN2_F - l_phi;
    }
}

// ---------------------------------------------------------------------------
// Kernel 4: mean -> scalar.
// ---------------------------------------------------------------------------
__global__ __launch_bounds__(256) void mean_kernel(float* __restrict__ out) {
    const int tid = threadIdx.x;
    __shared__ float sh[256];
    float s = 0.f;
    for (int i = tid; i < B_ROWS; i += 256) s += g_nll[i];
    sh[tid] = s;
    __syncthreads();
    for (int o = 128; o > 0; o >>= 1) {
        if (tid < o) sh[tid] += sh[tid + o];
        __syncthreads();
    }
    if (tid == 0) out[0] = sh[0] * (1.0f / (float)B_ROWS);
}

// ---------------------------------------------------------------------------
extern "C" void kernel_launch(void* const* d_in, const int* in_sizes, int n_in,
                              void* d_out, int out_size) {
    const float* emb    = (const float*)d_in[0];
    const void*  labels = d_in[1];
    const float* weight = (const float*)d_in[2];
    float*       out    = (float*)d_out;

    cudaFuncSetAttribute(gemm_lse_h, cudaFuncAttributeMaxDynamicSharedMemorySize, SMEM_DYN);

    prepass_kernel<<<WBLK + EBLK + 1, 256>>>(weight, emb, labels);

    gemm_lse_h<<<NUM_CTAS, 256, SMEM_DYN>>>();

    finalize_rows_kernel<<<B_ROWS / 8, 256>>>(emb, labels, weight);
    mean_kernel<<<1, 256>>>(out);
}

// round 17
// speedup vs baseline: 1.3822x; 1.3822x over previous
#include <cuda_runtime.h>
#include <cuda_fp16.h>
#include <math.h>
#include <float.h>
#include <stdint.h>

// ---------------- problem constants ----------------
#define B_ROWS   1024
#define EMB_D    512
#define NCLASS   100000
#define CT       128                              // class tile (N)
#define NTILES   ((NCLASS + CT - 1) / CT)         // 782
#define MBLK     8                                // B_ROWS / 128
#define SCALE_F  30.0f
#define LOG2E_F  1.4426950408889634f
#define LN2_F    0.6931471805599453f

// ArcFace margin constants (margin = 0.3)
#define COS_M 0.9553364891256061f
#define SIN_M 0.2955202066613396f
#define TH_C  (-0.9553364891256061f)
#define MM_C  0.08865606199840186f

// ---------------- scratch ----------------
// g_wh holds weight * (30*log2(e)/||w||): GEMM accumulators are log2-logits.
__device__ __half  g_wh[(size_t)NCLASS * EMB_D];
__device__ __half  g_eh[B_ROWS * EMB_D];          // fp16 embeddings
__device__ float   g_inv_norm[NCLASS];            // 30/||w|| (exact label path)
__device__ float2  g_ms[(size_t)B_ROWS * NTILES]; // per-tile {max, sum2^} (log2)
__device__ float   g_nll[B_ROWS];
__device__ int     g_lab_is64;
__device__ int     g_done;                        // finalize completion counter

// ---------------- helpers ----------------
__device__ __forceinline__ uint32_t smem_u32(const void* p) {
    uint32_t a;
    asm("{ .reg .u64 t; cvta.to.shared.u64 t, %1; cvt.u32.u64 %0, t; }" : "=r"(a) : "l"(p));
    return a;
}
__device__ __forceinline__ void cp16(uint32_t dst, const void* src, int bytes) {
    asm volatile("cp.async.cg.shared.global [%0], [%1], 16, %2;" :: "r"(dst), "l"(src), "r"(bytes));
}
__device__ __forceinline__ void cp16u(uint32_t dst, const void* src) {
    asm volatile("cp.async.cg.shared.global [%0], [%1], 16;" :: "r"(dst), "l"(src));
}
#define CP_COMMIT()  asm volatile("cp.async.commit_group;" ::: "memory")
#define CP_WAIT(n)   asm volatile("cp.async.wait_group %0;" :: "n"(n) : "memory")

__device__ __forceinline__ void mma_16816(float* c, const uint32_t* a, uint32_t b0, uint32_t b1) {
    asm volatile(
        "mma.sync.aligned.m16n8k16.row.col.f32.f16.f16.f32 "
        "{%0,%1,%2,%3}, {%4,%5,%6,%7}, {%8,%9}, {%0,%1,%2,%3};"
        : "+f"(c[0]), "+f"(c[1]), "+f"(c[2]), "+f"(c[3])
        : "r"(a[0]), "r"(a[1]), "r"(a[2]), "r"(a[3]), "r"(b0), "r"(b1));
}
__device__ __forceinline__ void ldm_x4(uint32_t* r, uint32_t addr) {
    asm volatile("ldmatrix.sync.aligned.m8n8.x4.shared.b16 {%0,%1,%2,%3}, [%4];"
                 : "=r"(r[0]), "=r"(r[1]), "=r"(r[2]), "=r"(r[3]) : "r"(addr));
}

// smem geometry: fp16, K-chunk 64, padded row stride 72 halves (144 B)
// stage = A(128 rows) + B(128 rows); 3-stage ring, 1 barrier per chunk.
#define RS_H        72
#define TILE_B      (128 * RS_H * 2)               // 18432 B per operand
#define STAGE_B     (2 * TILE_B)                   // 36864 B
#define NSTAGE      3
#define PART_OFF    (NSTAGE * STAGE_B)             // 110592
#define SMEM_DYN    (PART_OFF + 2048)              // 112640 B (2 CTAs/SM: 220 KB)

// ---------------------------------------------------------------------------
// Kernel 0: fused prepass (one launch):
//  blocks [0, WBLK)       : per-class norm + fp16 convert (30*log2e/||w|| folded)
//  blocks [WBLK, WBLK+EB) : embeddings fp32 -> fp16
//  block  WBLK+EBLK       : labels dtype probe + reset g_done
// ---------------------------------------------------------------------------
#define WBLK ((NCLASS + 7) / 8)                    // 12500
#define EBLK (B_ROWS * EMB_D / 4 / 256)            // 512

__global__ __launch_bounds__(256) void prepass_kernel(const float* __restrict__ weight,
                                                      const float* __restrict__ emb,
                                                      const void* __restrict__ labels) {
    if (blockIdx.x < WBLK) {
        int gid  = blockIdx.x * 256 + threadIdx.x;
        int c    = gid >> 5;
        int lane = gid & 31;
        if (c >= NCLASS) return;
        const float* w = weight + (size_t)c * EMB_D;
        float4 v[4];
        float s = 0.f;
        #pragma unroll
        for (int i = 0; i < 4; i++) {
            v[i] = *(const float4*)&w[lane * 4 + i * 128];
            s += v[i].x * v[i].x + v[i].y * v[i].y + v[i].z * v[i].z + v[i].w * v[i].w;
        }
        #pragma unroll
        for (int o = 16; o > 0; o >>= 1) s += __shfl_xor_sync(0xffffffffu, s, o);
        float r  = rsqrtf(s);
        if (lane == 0) g_inv_norm[c] = SCALE_F * r;
        float sc = SCALE_F * LOG2E_F * r;          // log2-domain fold
        __half* dst = g_wh + (size_t)c * EMB_D;
        #pragma unroll
        for (int i = 0; i < 4; i++) {
            __half2 h0 = __floats2half2_rn(v[i].x * sc, v[i].y * sc);
            __half2 h1 = __floats2half2_rn(v[i].z * sc, v[i].w * sc);
            *(uint2*)&dst[lane * 4 + i * 128] = make_uint2(*(uint32_t*)&h0, *(uint32_t*)&h1);
        }
    } else if (blockIdx.x < WBLK + EBLK) {
        int i = (blockIdx.x - WBLK) * 256 + threadIdx.x;   // one float4 per thread
        float4 v = *(const float4*)&emb[i * 4];
        __half2 h0 = __floats2half2_rn(v.x, v.y);
        __half2 h1 = __floats2half2_rn(v.z, v.w);
        *(uint2*)&g_eh[i * 4] = make_uint2(*(uint32_t*)&h0, *(uint32_t*)&h1);
    } else {
        // labels dtype probe: read first 512 elements as int64 (4 KB, safe
        // even for an int32 buffer). All in range -> int64, else int32.
        __shared__ int bad;
        if (threadIdx.x == 0) { bad = 0; g_done = 0; }     // reset counter (graph replay)
        __syncthreads();
        #pragma unroll
        for (int i = 0; i < 2; i++) {
            long long v = ((const long long*)labels)[threadIdx.x * 2 + i];
            if (v < 0 || v >= NCLASS) atomicOr(&bad, 1);
        }
        __syncthreads();
        if (threadIdx.x == 0) g_lab_is64 = bad ? 0 : 1;
    }
}

// ---------------------------------------------------------------------------
// Kernel 1: fp16 mma GEMM 128x128x512 + fused logsumexp (log2 domain).
// grid=(MBLK, NTILES), 256 threads (8 warps: 4M x 2N), warp tile 32x64,
// 3-stage cp.async ring, ONE __syncthreads per K-chunk, 2 CTAs/SM.
// Full class tiles (781/782) use unguarded fills + unmasked epilogue.
// (Byte-identical mainloop to the 333.9us baseline; only the partial store
//  format changed to interleaved float2.)
// ---------------------------------------------------------------------------
__global__ __launch_bounds__(256, 2) void gemm_lse_h(void) {
    extern __shared__ __align__(16) char smc[];
    float*  sm_pm = (float*)(smc + PART_OFF);          // [128][2]
    float*  sm_ps = sm_pm + 256;

    const int tid    = threadIdx.x;
    const int m_base = blockIdx.x * 128;
    const int c0     = blockIdx.y * CT;
    const bool full  = (c0 + CT) <= NCLASS;            // uniform per CTA

    const int wid  = tid >> 5, lane = tid & 31;
    const int wm   = wid & 3;
    const int wn   = wid >> 2;
    const int g    = lane >> 2, tig = lane & 3;

    const uint32_t smem_base = smem_u32(smc);

    // ldmatrix per-lane byte offsets within a stage
    const uint32_t a_off = ((uint32_t)(wm * 32 + (lane & 7) + ((lane >> 3) & 1) * 8) * RS_H
                            + ((lane >> 4) & 1) * 8) * 2;
    const uint32_t b_off = (uint32_t)TILE_B
                         + ((uint32_t)(wn * 64 + (lane & 7) + ((lane >> 4) & 1) * 8) * RS_H
                            + ((lane >> 3) & 1) * 8) * 2;

    // per-thread fill coordinates (A/B loops statically split)
    const int fr = tid >> 3;                     // base row 0..31
    const int fu = tid & 7;                      // 16B unit
    const __half* eA = g_eh + (size_t)(m_base + fr) * EMB_D + fu * 8;

    auto load_stage = [&](int kt, uint32_t sa) {
        const int k0 = kt * 64;
        const uint32_t sb = sa + TILE_B;
        #pragma unroll
        for (int i = 0; i < 4; i++) {                       // A rows fr+32i
            cp16u(sa + ((fr + i * 32) * RS_H + fu * 8) * 2,
                  eA + (size_t)(i * 32) * EMB_D + k0);
        }
        if (full) {
            #pragma unroll
            for (int i = 0; i < 4; i++) {                   // B rows fr+32i, no guards
                int rr = fr + i * 32;
                cp16u(sb + (rr * RS_H + fu * 8) * 2,
                      g_wh + (size_t)(c0 + rr) * EMB_D + k0 + fu * 8);
            }
        } else {
            #pragma unroll
            for (int i = 0; i < 4; i++) {
                int rr = fr + i * 32;
                int c  = c0 + rr;
                int cc = (c < NCLASS) ? c : (NCLASS - 1);
                cp16(sb + (rr * RS_H + fu * 8) * 2,
                     g_wh + (size_t)cc * EMB_D + k0 + fu * 8,
                     (c < NCLASS) ? 16 : 0);
            }
        }
        CP_COMMIT();
    };

    float acc[2][8][4];
    #pragma unroll
    for (int mi = 0; mi < 2; mi++)
        #pragma unroll
        for (int ni = 0; ni < 8; ni++)
            #pragma unroll
            for (int q = 0; q < 4; q++) acc[mi][ni][q] = 0.f;

    auto consume = [&](uint32_t cur) {
        const uint32_t sA = cur + a_off;
        const uint32_t sB = cur + b_off;
        #pragma unroll
        for (int ks = 0; ks < 4; ks++) {
            const uint32_t kb = (uint32_t)ks * 32;     // 16 halves
            uint32_t a[2][4];
            ldm_x4(a[0], sA + kb);
            ldm_x4(a[1], sA + (16 * RS_H) * 2 + kb);
            #pragma unroll
            for (int nip = 0; nip < 4; nip++) {
                uint32_t br[4];
                ldm_x4(br, sB + (uint32_t)(nip * 16 * RS_H) * 2 + kb);
                mma_16816(acc[0][2 * nip],     a[0], br[0], br[1]);
                mma_16816(acc[1][2 * nip],     a[1], br[0], br[1]);
                mma_16816(acc[0][2 * nip + 1], a[0], br[2], br[3]);
                mma_16816(acc[1][2 * nip + 1], a[1], br[2], br[3]);
            }
        }
    };

    const uint32_t ring_end = smem_base + NSTAGE * STAGE_B;
    uint32_t cur = smem_base;                    // stage of chunk kt
    uint32_t pf  = smem_base + 2 * STAGE_B;      // stage for chunk kt+2

    load_stage(0, smem_base);
    load_stage(1, smem_base + STAGE_B);

    #pragma unroll 1
    for (int kt = 0; kt < 6; kt++) {
        CP_WAIT(1);
        __syncthreads();
        load_stage(kt + 2, pf);                  // slot held chunk kt-1 (consumed)
        consume(cur);
        cur += STAGE_B; if (cur == ring_end) cur = smem_base;
        pf  += STAGE_B; if (pf  == ring_end) pf  = smem_base;
    }
    CP_WAIT(1);
    __syncthreads();
    consume(cur);
    cur += STAGE_B; if (cur == ring_end) cur = smem_base;
    CP_WAIT(0);
    __syncthreads();
    consume(cur);

    // ---- epilogue: per-row (max, sum 2^) in log2 domain.
    #pragma unroll
    for (int mi = 0; mi < 2; mi++) {
        #pragma unroll
        for (int half = 0; half < 2; half++) {
            const int row = wm * 32 + mi * 16 + half * 8 + g;
            float lv[16];
            float mx = -FLT_MAX;
            #pragma unroll
            for (int ni = 0; ni < 8; ni++) {
                float v0 = acc[mi][ni][half * 2 + 0];
                float v1 = acc[mi][ni][half * 2 + 1];
                if (!full) {
                    int col = wn * 64 + ni * 8 + 2 * tig;
                    if (c0 + col     >= NCLASS) v0 = -FLT_MAX;
                    if (c0 + col + 1 >= NCLASS) v1 = -FLT_MAX;
                }
                lv[ni * 2]     = v0;
                lv[ni * 2 + 1] = v1;
                mx = fmaxf(mx, fmaxf(v0, v1));
            }
            float ss = 0.f;
            #pragma unroll
            for (int j = 0; j < 16; j++) ss += exp2f(lv[j] - mx);
            #pragma unroll
            for (int d = 1; d <= 2; d <<= 1) {
                float om = __shfl_xor_sync(0xffffffffu, mx, d);
                float os = __shfl_xor_sync(0xffffffffu, ss, d);
                float nm = fmaxf(mx, om);
                ss = ss * exp2f(mx - nm) + os * exp2f(om - nm);
                mx = nm;
            }
            if (tig == 0) {
                sm_pm[row * 2 + wn] = mx;
                sm_ps[row * 2 + wn] = ss;
            }
        }
    }
    __syncthreads();

    if (tid < 128) {
        float m0 = sm_pm[tid * 2], m1 = sm_pm[tid * 2 + 1];
        float s0 = sm_ps[tid * 2], s1 = sm_ps[tid * 2 + 1];
        float M = fmaxf(m0, m1);
        float S = s0 * exp2f(m0 - M) + s1 * exp2f(m1 - M);
        g_ms[(size_t)(m_base + tid) * NTILES + blockIdx.y] = make_float2(M, S);
    }
}

// ---------------------------------------------------------------------------
// Kernel 3: one WARP per batch row: single-pass online combine of tile
// partials + exact label cosine + ArcFace correction. The LAST block also
// performs the deterministic mean reduction (fixed-order tree over g_nll).
// grid = B_ROWS/8, 256 threads.
// ---------------------------------------------------------------------------
__global__ __launch_bounds__(256) void finalize_rows_kernel(const float* __restrict__ emb,
                                                            const void* __restrict__ labels,
                                                            const float* __restrict__ weight,
                                                            float* __restrict__ out) {
    const int wid  = threadIdx.x >> 5;
    const int lane = threadIdx.x & 31;
    const int b    = blockIdx.x * 8 + wid;

    long long lab;
    if (g_lab_is64) lab = ((const long long*)labels)[b];
    else            lab = (long long)((const int*)labels)[b];
    if (lab < 0) lab = 0;
    if (lab >= NCLASS) lab = NCLASS - 1;

    // exact fp32 label dot
    const float* e = emb + (size_t)b * EMB_D;
    const float* w = weight + (size_t)lab * EMB_D;
    float dot = 0.f;
    #pragma unroll
    for (int i = 0; i < 4; i++) {
        float4 ev = *(const float4*)&e[lane * 4 + i * 128];
        float4 wv = *(const float4*)&w[lane * 4 + i * 128];
        dot += ev.x * wv.x + ev.y * wv.y + ev.z * wv.z + ev.w * wv.w;
    }
    #pragma unroll
    for (int o = 16; o > 0; o >>= 1) dot += __shfl_xor_sync(0xffffffffu, dot, o);

    // single-pass online (max, sum) over tiles (log2 domain)
    const float2* gms = g_ms + (size_t)b * NTILES;
    float M = -FLT_MAX, S = 0.f;
    for (int t = lane; t < NTILES; t += 32) {
        float2 v = gms[t];
        float nm = fmaxf(M, v.x);
        S = S * exp2f(M - nm) + v.y * exp2f(v.x - nm);
        M = nm;
    }
    #pragma unroll
    for (int o = 16; o > 0; o >>= 1) {
        float om = __shfl_xor_sync(0xffffffffu, M, o);
        float os = __shfl_xor_sync(0xffffffffu, S, o);
        float nm = fmaxf(M, om);
        S = S * exp2f(M - nm) + os * exp2f(om - nm);
        M = nm;
    }

    if (lane == 0) {
        float cv = dot * g_inv_norm[lab] * (1.0f / SCALE_F);     // cosine
        float l_cos = SCALE_F * cv;                              // natural domain
        float sine  = sqrtf(fmaxf(0.f, fminf(1.f, 1.f - cv * cv)));
        float phi   = cv * COS_M - sine * SIN_M;
        if (!(cv > TH_C)) phi = cv - MM_C;
        float l_phi = SCALE_F * phi;
        float Sc = S - exp2f(l_cos * LOG2E_F - M) + exp2f(l_phi * LOG2E_F - M);
        g_nll[b] = (M + log2f(Sc)) * LN2_F - l_phi;
    }

    // ---- last-block deterministic mean ----
    __shared__ int  is_last;
    __shared__ float sh[256];
    __syncthreads();
    if (threadIdx.x == 0) {
        __threadfence();                               // publish g_nll writes
        int prev = atomicAdd(&g_done, 1);
        is_last = (prev == gridDim.x - 1) ? 1 : 0;
    }
    __syncthreads();
    if (!is_last) return;
    __threadfence();                                   // acquire all g_nll

    float s = 0.f;
    #pragma unroll
    for (int i = 0; i < 4; i++) s += g_nll[threadIdx.x + i * 256];
    sh[threadIdx.x] = s;
    __syncthreads();
    for (int o = 128; o > 0; o >>= 1) {
        if (threadIdx.x < o) sh[threadIdx.x] += sh[threadIdx.x + o];
        __syncthreads();
    }
    if (threadIdx.x == 0) out[0] = sh[0] * (1.0f / (float)B_ROWS);
}

// ---------------------------------------------------------------------------
extern "C" void kernel_launch(void* const* d_in, const int* in_sizes, int n_in,
                              void* d_out, int out_size) {
    const float* emb    = (const float*)d_in[0];
    const void*  labels = d_in[1];
    const float* weight = (const float*)d_in[2];
    float*       out    = (float*)d_out;

    cudaFuncSetAttribute(gemm_lse_h, cudaFuncAttributeMaxDynamicSharedMemorySize, SMEM_DYN);

    prepass_kernel<<<WBLK + EBLK + 1, 256>>>(weight, emb, labels);

    dim3 grid(MBLK, NTILES);
    gemm_lse_h<<<grid, 256, SMEM_DYN>>>();

    finalize_rows_kernel<<<B_ROWS / 8, 256>>>(emb, labels, weight, out);
}